// round 2
// baseline (speedup 1.0000x reference)
#include <cuda_runtime.h>
#include <math.h>

// Problem constants
#define SS  4
#define NN  32768
#define DD  256
#define KK  512
#define NHH 4
#define HDD 64
#define FF  1024

// ---------------- scratch (device globals; no runtime allocation) ----------------
__device__ float g_x   [SS*KK*DD];    // pooled patch summaries (then normalized)
__device__ int   g_cnt [SS*KK];
__device__ float g_y   [SS*KK*DD];    // LN output (reused for LN1 and LN2)
__device__ float g_q   [SS*KK*DD];
__device__ float g_k   [SS*KK*DD];
__device__ float g_v   [SS*KK*DD];
__device__ float g_kv  [SS*NHH*HDD*HDD];
__device__ float g_ksum[SS*NHH*HDD];
__device__ float g_attn[SS*KK*DD];
__device__ float g_x2  [SS*KK*DD];    // after attention residual
__device__ float g_h   [SS*KK*FF];    // ffn hidden
__device__ float g_p2  [SS*KK*DD];    // psu @ mlp_W1[256:512] + mlp_b1 (per patch)
__device__ float g_hid [SS*NN*DD];    // node MLP hidden (gelu output)

// ---------------- small device helpers ----------------
__device__ __forceinline__ float geluf(float x) {
    return 0.5f * x * (1.0f + erff(x * 0.70710678118654752440f));
}
__device__ __forceinline__ float phif(float x) {   // elu(x)+1
    return x > 0.0f ? x + 1.0f : expf(x);
}

// ---------------- kernels ----------------
__global__ void k_zero() {
    int i = blockIdx.x * blockDim.x + threadIdx.x;   // grid covers SS*KK*DD
    if (i < SS*KK*DD) g_x[i] = 0.0f;
    if (i < SS*KK)    g_cnt[i] = 0;
}

__global__ void k_pool(const float* __restrict__ H, const int* __restrict__ pid) {
    int b = blockIdx.x;          // 0 .. SS*NN-1 (node index)
    int d = threadIdx.x;         // 0 .. 255
    int s = b >> 15;             // NN = 32768
    int p = __ldg(&pid[b]);
    atomicAdd(&g_x[((size_t)(s*KK + p))*DD + d], __ldg(&H[(size_t)b*DD + d]));
    if (d == 0) atomicAdd(&g_cnt[s*KK + p], 1);
}

__global__ void k_finalize() {
    int r = blockIdx.x;          // 0 .. SS*KK-1
    int d = threadIdx.x;
    int c = g_cnt[r];
    float inv = 1.0f / (float)(c > 1 ? c : 1);
    g_x[(size_t)r*DD + d] *= inv;
}

__global__ void k_ln(const float* __restrict__ in, const float* __restrict__ gw,
                     const float* __restrict__ bw, float* __restrict__ out) {
    int r = blockIdx.x, d = threadIdx.x;
    float v = in[(size_t)r*DD + d];
    __shared__ float s1[8], s2[8];
    __shared__ float smu, sri;
    float a = v, b = v * v;
    #pragma unroll
    for (int o = 16; o > 0; o >>= 1) {
        a += __shfl_down_sync(0xffffffffu, a, o);
        b += __shfl_down_sync(0xffffffffu, b, o);
    }
    if ((d & 31) == 0) { s1[d >> 5] = a; s2[d >> 5] = b; }
    __syncthreads();
    if (d == 0) {
        float sa = 0.f, sb = 0.f;
        #pragma unroll
        for (int i = 0; i < 8; i++) { sa += s1[i]; sb += s2[i]; }
        float m   = sa * (1.0f / DD);
        float var = sb * (1.0f / DD) - m * m;
        smu = m;
        sri = rsqrtf(var + 1e-5f);
    }
    __syncthreads();
    out[(size_t)r*DD + d] = (v - smu) * sri * gw[d] + bw[d];
}

// Generic 64x64 tiled SGEMM:  C[M,N] = epilogue(A[M,Kd] @ B[Kd,N] + bias)
// modes: 0 = +bias; 1 = phi; 2 = phi*mask; 3 = *mask; 4 = +res; 5 = gelu
__global__ __launch_bounds__(256) void k_gemm64(
    const float* __restrict__ A, const float* __restrict__ B,
    const float* __restrict__ bias, float* __restrict__ C,
    int M, int N, int Kd, int mode, const float* __restrict__ res)
{
    __shared__ float As[16][64];
    __shared__ float Bs[16][64];
    int t  = threadIdx.x;
    int n0 = blockIdx.x * 64, m0 = blockIdx.y * 64;
    int tx = t & 15, ty = t >> 4;
    float acc[4][4] = {};
    int arow = t >> 2, ak = (t & 3) * 4;
    int bk   = t >> 4, bn = (t & 15) * 4;

    for (int k0 = 0; k0 < Kd; k0 += 16) {
        float4 av = *(const float4*)&A[(size_t)(m0 + arow)*Kd + k0 + ak];
        As[ak+0][arow] = av.x; As[ak+1][arow] = av.y;
        As[ak+2][arow] = av.z; As[ak+3][arow] = av.w;
        *(float4*)&Bs[bk][bn] = *(const float4*)&B[(size_t)(k0 + bk)*N + n0 + bn];
        __syncthreads();
        #pragma unroll
        for (int kk = 0; kk < 16; kk++) {
            float4 a4 = *(const float4*)&As[kk][ty*4];
            float4 b4 = *(const float4*)&Bs[kk][tx*4];
            float aa[4] = {a4.x, a4.y, a4.z, a4.w};
            float bb[4] = {b4.x, b4.y, b4.z, b4.w};
            #pragma unroll
            for (int i = 0; i < 4; i++)
                #pragma unroll
                for (int j = 0; j < 4; j++)
                    acc[i][j] += aa[i] * bb[j];
        }
        __syncthreads();
    }

    #pragma unroll
    for (int i = 0; i < 4; i++) {
        int m = m0 + ty*4 + i;
        float mask = 1.0f;
        if (mode == 2 || mode == 3) mask = (g_cnt[m] > 0) ? 1.0f : 0.0f;
        #pragma unroll
        for (int j = 0; j < 4; j++) {
            int n = n0 + tx*4 + j;
            float v = acc[i][j] + bias[n];
            if      (mode == 1) v = phif(v);
            else if (mode == 2) v = phif(v) * mask;
            else if (mode == 3) v = v * mask;
            else if (mode == 4) v = v + res[(size_t)m*N + n];
            else if (mode == 5) v = geluf(v);
            C[(size_t)m*N + n] = v;
        }
    }
}

// kv[s,h,d,e] = sum_k k[s,k,h,d]*v[s,k,h,e];  ksum[s,h,d] = sum_k k[s,k,h,d]
__global__ __launch_bounds__(256) void k_kvsum() {
    int b = blockIdx.x;                  // s*NHH + h
    int s = b >> 2, h = b & 3;
    int t = threadIdx.x, tx = t & 15, ty = t >> 4;
    __shared__ float ks[8][64], vs[8][64];
    float acc[4][4] = {};
    float ksl = 0.0f;
    const float* kp = g_k + ((size_t)s*KK*NHH + h)*HDD;
    const float* vp = g_v + ((size_t)s*KK*NHH + h)*HDD;

    for (int k0 = 0; k0 < KK; k0 += 8) {
        #pragma unroll
        for (int u = 0; u < 2; u++) {
            int idx = t + u*256; int i = idx >> 6, d = idx & 63;
            ks[i][d] = kp[(size_t)(k0 + i)*NHH*HDD + d];
            vs[i][d] = vp[(size_t)(k0 + i)*NHH*HDD + d];
        }
        __syncthreads();
        if (t < 64) {
            #pragma unroll
            for (int i = 0; i < 8; i++) ksl += ks[i][t];
        }
        #pragma unroll
        for (int i = 0; i < 8; i++) {
            float kd[4], ve[4];
            #pragma unroll
            for (int j = 0; j < 4; j++) { kd[j] = ks[i][ty*4+j]; ve[j] = vs[i][tx*4+j]; }
            #pragma unroll
            for (int a = 0; a < 4; a++)
                #pragma unroll
                for (int c = 0; c < 4; c++)
                    acc[a][c] += kd[a] * ve[c];
        }
        __syncthreads();
    }
    if (t < 64) g_ksum[(size_t)b*64 + t] = ksl;
    #pragma unroll
    for (int a = 0; a < 4; a++)
        #pragma unroll
        for (int c = 0; c < 4; c++)
            g_kv[((size_t)b*64 + ty*4 + a)*64 + tx*4 + c] = acc[a][c];
}

// attn[s,k,h,e] = (sum_d q*kv[d,e]) / (sum_d q*ksum[d] + eps)
__global__ void k_attn() {
    int r = blockIdx.x;                  // s*KK + k
    int s = r / KK;
    int t = threadIdx.x;
    __shared__ float qs[256];
    qs[t] = g_q[(size_t)r*DD + t];
    __syncthreads();
    int h = t >> 6, e = t & 63;
    const float* kvp = g_kv   + (size_t)(s*NHH + h)*HDD*HDD;
    const float* ksp = g_ksum + (size_t)(s*NHH + h)*HDD;
    float num = 0.f, den = 0.f;
    #pragma unroll 8
    for (int d = 0; d < 64; d++) {
        float q = qs[h*64 + d];
        num += q * kvp[d*64 + e];
        den += q * ksp[d];
    }
    g_attn[(size_t)r*DD + t] = num / (den + 1e-6f);
}

// Big 128x128x16 SGEMM, 8x8 per thread.
// mode 10: C = gelu(acc + P2[s, pid[m], :])      (aux = P2, pid used)
// mode 11: C = acc + bias + aux[m,:]             (aux = H residual)
__global__ __launch_bounds__(256) void k_gemm128(
    const float* __restrict__ A, const float* __restrict__ B,
    float* __restrict__ C, int M, int N, int Kd, int mode,
    const float* __restrict__ aux, const float* __restrict__ bias,
    const int* __restrict__ pid)
{
    __shared__ float As[16][128];
    __shared__ float Bs[16][128];
    int t  = threadIdx.x;
    int n0 = blockIdx.x * 128, m0 = blockIdx.y * 128;
    int tx = t & 15, ty = t >> 4;
    float acc[8][8] = {};
    int arow = t >> 1, ak = (t & 1) * 8;    // each thread: 2 float4 of A
    int brow = t >> 4, bn = (t & 15) * 8;   // each thread: 2 float4 of B

    for (int k0 = 0; k0 < Kd; k0 += 16) {
        float4 av0 = *(const float4*)&A[(size_t)(m0 + arow)*Kd + k0 + ak];
        float4 av1 = *(const float4*)&A[(size_t)(m0 + arow)*Kd + k0 + ak + 4];
        As[ak+0][arow] = av0.x; As[ak+1][arow] = av0.y;
        As[ak+2][arow] = av0.z; As[ak+3][arow] = av0.w;
        As[ak+4][arow] = av1.x; As[ak+5][arow] = av1.y;
        As[ak+6][arow] = av1.z; As[ak+7][arow] = av1.w;
        *(float4*)&Bs[brow][bn]     = *(const float4*)&B[(size_t)(k0 + brow)*N + n0 + bn];
        *(float4*)&Bs[brow][bn + 4] = *(const float4*)&B[(size_t)(k0 + brow)*N + n0 + bn + 4];
        __syncthreads();
        #pragma unroll
        for (int kk = 0; kk < 16; kk++) {
            float a[8], b[8];
            *(float4*)&a[0] = *(const float4*)&As[kk][ty*8];
            *(float4*)&a[4] = *(const float4*)&As[kk][ty*8 + 4];
            *(float4*)&b[0] = *(const float4*)&Bs[kk][tx*8];
            *(float4*)&b[4] = *(const float4*)&Bs[kk][tx*8 + 4];
            #pragma unroll
            for (int i = 0; i < 8; i++)
                #pragma unroll
                for (int j = 0; j < 8; j++)
                    acc[i][j] += a[i] * b[j];
        }
        __syncthreads();
    }

    if (mode == 10) {
        #pragma unroll
        for (int i = 0; i < 8; i++) {
            int m = m0 + ty*8 + i;
            int s = m >> 15;                 // NN = 32768
            int p = pid[m];
            const float* p2 = aux + ((size_t)(s*KK + p))*DD;
            #pragma unroll
            for (int j = 0; j < 8; j++) {
                int col = n0 + tx*8 + j;
                float v = acc[i][j] + p2[col];
                C[(size_t)m*N + col] = geluf(v);
            }
        }
    } else {
        #pragma unroll
        for (int i = 0; i < 8; i++) {
            int m = m0 + ty*8 + i;
            #pragma unroll
            for (int j = 0; j < 8; j++) {
                int col = n0 + tx*8 + j;
                C[(size_t)m*N + col] = acc[i][j] + bias[col] + aux[(size_t)m*N + col];
            }
        }
    }
}

// ---------------- launch ----------------
extern "C" void kernel_launch(void* const* d_in, const int* in_sizes, int n_in,
                              void* d_out, int out_size) {
    (void)in_sizes; (void)n_in; (void)out_size;
    const float* H    = (const float*)d_in[0];
    const int*   pid  = (const int*)  d_in[1];
    const float* ln1g = (const float*)d_in[2];
    const float* ln1b = (const float*)d_in[3];
    const float* Wq   = (const float*)d_in[4];
    const float* bq   = (const float*)d_in[5];
    const float* Wk   = (const float*)d_in[6];
    const float* bk   = (const float*)d_in[7];
    const float* Wv   = (const float*)d_in[8];
    const float* bv   = (const float*)d_in[9];
    const float* Wo   = (const float*)d_in[10];
    const float* bo   = (const float*)d_in[11];
    const float* ln2g = (const float*)d_in[12];
    const float* ln2b = (const float*)d_in[13];
    const float* fW1  = (const float*)d_in[14];
    const float* fb1  = (const float*)d_in[15];
    const float* fW2  = (const float*)d_in[16];
    const float* fb2  = (const float*)d_in[17];
    const float* mW1  = (const float*)d_in[18];
    const float* mb1  = (const float*)d_in[19];
    const float* mW2  = (const float*)d_in[20];
    const float* mb2  = (const float*)d_in[21];

    float* out = (float*)d_out;
    float* psu = out + (size_t)SS*NN*DD;

    float *p_x, *p_y, *p_q, *p_k, *p_v, *p_attn, *p_x2, *p_h, *p_p2, *p_hid;
    cudaGetSymbolAddress((void**)&p_x,    g_x);
    cudaGetSymbolAddress((void**)&p_y,    g_y);
    cudaGetSymbolAddress((void**)&p_q,    g_q);
    cudaGetSymbolAddress((void**)&p_k,    g_k);
    cudaGetSymbolAddress((void**)&p_v,    g_v);
    cudaGetSymbolAddress((void**)&p_attn, g_attn);
    cudaGetSymbolAddress((void**)&p_x2,   g_x2);
    cudaGetSymbolAddress((void**)&p_h,    g_h);
    cudaGetSymbolAddress((void**)&p_p2,   g_p2);
    cudaGetSymbolAddress((void**)&p_hid,  g_hid);

    // 1) pooling
    k_zero<<<(SS*KK*DD + 255)/256, 256>>>();
    k_pool<<<SS*NN, 256>>>(H, pid);
    k_finalize<<<SS*KK, 256>>>();

    // 2) patch transformer
    k_ln<<<SS*KK, 256>>>(p_x, ln1g, ln1b, p_y);
    dim3 g64(DD/64, (SS*KK)/64);               // (4, 32)
    k_gemm64<<<g64, 256>>>(p_y, Wq, bq, p_q, SS*KK, DD, DD, 1, nullptr);
    k_gemm64<<<g64, 256>>>(p_y, Wk, bk, p_k, SS*KK, DD, DD, 2, nullptr);
    k_gemm64<<<g64, 256>>>(p_y, Wv, bv, p_v, SS*KK, DD, DD, 3, nullptr);
    k_kvsum<<<SS*NHH, 256>>>();
    k_attn<<<SS*KK, 256>>>();
    k_gemm64<<<g64, 256>>>(p_attn, Wo, bo, p_x2, SS*KK, DD, DD, 4, p_x);
    k_ln<<<SS*KK, 256>>>(p_x2, ln2g, ln2b, p_y);
    dim3 gf1(FF/64, (SS*KK)/64);               // (16, 32)
    k_gemm64<<<gf1, 256>>>(p_y, fW1, fb1, p_h, SS*KK, FF, DD, 5, nullptr);
    k_gemm64<<<g64, 256>>>(p_h, fW2, fb2, psu, SS*KK, DD, FF, 4, p_x2);

    // 3) node MLP: hidden = gelu(H@W1[:256] + (psu@W1[256:]+b1)[pid])
    k_gemm64<<<g64, 256>>>(psu, mW1 + DD*DD, mb1, p_p2, SS*KK, DD, DD, 0, nullptr);
    dim3 gb(DD/128, (SS*NN)/128);              // (2, 1024)
    k_gemm128<<<gb, 256>>>(H,     mW1, p_hid, SS*NN, DD, DD, 10, p_p2, nullptr, pid);
    k_gemm128<<<gb, 256>>>(p_hid, mW2, out,   SS*NN, DD, DD, 11, H,    mb2,     pid);
}

// round 4
// speedup vs baseline: 1.6855x; 1.6855x over previous
#include <cuda_runtime.h>
#include <cuda_bf16.h>
#include <math.h>
#include <stdint.h>

// Problem constants
#define SS  4
#define NN  32768
#define DD  256
#define KK  512
#define NHH 4
#define HDD 64
#define FF  1024

// ---------------- scratch (device globals; no runtime allocation) ----------------
__device__ float g_x   [SS*KK*DD];
__device__ int   g_cnt [SS*KK];
__device__ float g_y   [SS*KK*DD];
__device__ float g_q   [SS*KK*DD];
__device__ float g_k   [SS*KK*DD];
__device__ float g_v   [SS*KK*DD];
__device__ float g_kv  [SS*NHH*HDD*HDD];
__device__ float g_ksum[SS*NHH*HDD];
__device__ float g_attn[SS*KK*DD];
__device__ float g_x2  [SS*KK*DD];
__device__ float g_h   [SS*KK*FF];
__device__ float g_p2  [SS*KK*DD];
__device__ float g_hid [SS*NN*DD];          // node MLP hidden (fp32)
__device__ __nv_bfloat16 g_w1h[DD*DD];      // W1a^T hi  [n][k]
__device__ __nv_bfloat16 g_w1l[DD*DD];      // W1a^T lo
__device__ __nv_bfloat16 g_w2h[DD*DD];      // W2^T hi
__device__ __nv_bfloat16 g_w2l[DD*DD];      // W2^T lo

// ---------------- small device helpers ----------------
__device__ __forceinline__ float geluf(float x) {
    return 0.5f * x * (1.0f + erff(x * 0.70710678118654752440f));
}
__device__ __forceinline__ float phif(float x) {   // elu(x)+1
    return x > 0.0f ? x + 1.0f : expf(x);
}
__device__ __forceinline__ uint32_t pack_bf2(float a, float b) {
    __nv_bfloat162 t = __floats2bfloat162_rn(a, b);   // a -> low, b -> high
    return *(uint32_t*)&t;
}
__device__ __forceinline__ float bflo(uint32_t p) {
    __nv_bfloat162 b = *(__nv_bfloat162*)&p; return __bfloat162float(b.x);
}
__device__ __forceinline__ float bfhi(uint32_t p) {
    __nv_bfloat162 b = *(__nv_bfloat162*)&p; return __bfloat162float(b.y);
}
__device__ __forceinline__ uint32_t smem_u32(const void* p) {
    uint32_t a;
    asm("{ .reg .u64 t; cvta.to.shared.u64 t, %1; cvt.u32.u64 %0, t; }" : "=r"(a) : "l"(p));
    return a;
}
#define LDSM_X4(r0, r1, r2, r3, addr) \
    asm volatile("ldmatrix.sync.aligned.m8n8.x4.shared.b16 {%0,%1,%2,%3}, [%4];" \
                 : "=r"(r0), "=r"(r1), "=r"(r2), "=r"(r3) : "r"(addr))
#define MMA_BF16(d, a, b) \
    asm volatile("mma.sync.aligned.m16n8k16.row.col.f32.bf16.bf16.f32 " \
                 "{%0,%1,%2,%3},{%4,%5,%6,%7},{%8,%9},{%0,%1,%2,%3};" \
                 : "+f"((d)[0]), "+f"((d)[1]), "+f"((d)[2]), "+f"((d)[3]) \
                 : "r"((a)[0]), "r"((a)[1]), "r"((a)[2]), "r"((a)[3]), \
                   "r"((b)[0]), "r"((b)[1]))

// ---------------- kernels ----------------
__global__ void k_zero() {
    int i = blockIdx.x * blockDim.x + threadIdx.x;
    if (i < SS*KK*DD) g_x[i] = 0.0f;
    if (i < SS*KK)    g_cnt[i] = 0;
}

__global__ void k_prep_w(const float* __restrict__ W1, const float* __restrict__ W2) {
    int n = blockIdx.x, k = threadIdx.x;
    float v1 = W1[k*DD + n];            // W1a = mlp_W1[0:256, :]
    __nv_bfloat16 h1 = __float2bfloat16(v1);
    g_w1h[n*DD + k] = h1;
    g_w1l[n*DD + k] = __float2bfloat16(v1 - __bfloat162float(h1));
    float v2 = W2[k*DD + n];
    __nv_bfloat16 h2 = __float2bfloat16(v2);
    g_w2h[n*DD + k] = h2;
    g_w2l[n*DD + k] = __float2bfloat16(v2 - __bfloat162float(h2));
}

__global__ void k_pool(const float* __restrict__ H, const int* __restrict__ pid) {
    int b = blockIdx.x;
    int d = threadIdx.x;
    int s = b >> 15;
    int p = __ldg(&pid[b]);
    atomicAdd(&g_x[((size_t)(s*KK + p))*DD + d], __ldg(&H[(size_t)b*DD + d]));
    if (d == 0) atomicAdd(&g_cnt[s*KK + p], 1);
}

__global__ void k_finalize() {
    int r = blockIdx.x, d = threadIdx.x;
    int c = g_cnt[r];
    float inv = 1.0f / (float)(c > 1 ? c : 1);
    g_x[(size_t)r*DD + d] *= inv;
}

__global__ void k_ln(const float* __restrict__ in, const float* __restrict__ gw,
                     const float* __restrict__ bw, float* __restrict__ out) {
    int r = blockIdx.x, d = threadIdx.x;
    float v = in[(size_t)r*DD + d];
    __shared__ float s1[8], s2[8];
    __shared__ float smu, sri;
    float a = v, b = v * v;
    #pragma unroll
    for (int o = 16; o > 0; o >>= 1) {
        a += __shfl_down_sync(0xffffffffu, a, o);
        b += __shfl_down_sync(0xffffffffu, b, o);
    }
    if ((d & 31) == 0) { s1[d >> 5] = a; s2[d >> 5] = b; }
    __syncthreads();
    if (d == 0) {
        float sa = 0.f, sb = 0.f;
        #pragma unroll
        for (int i = 0; i < 8; i++) { sa += s1[i]; sb += s2[i]; }
        float m   = sa * (1.0f / DD);
        float var = sb * (1.0f / DD) - m * m;
        smu = m; sri = rsqrtf(var + 1e-5f);
    }
    __syncthreads();
    out[(size_t)r*DD + d] = (v - smu) * sri * gw[d] + bw[d];
}

// 64x64 tiled SGEMM for patch-level ops.
// modes: 0 = +bias; 1 = phi; 2 = phi*mask; 3 = *mask; 4 = +res; 5 = gelu
__global__ __launch_bounds__(256) void k_gemm64(
    const float* __restrict__ A, const float* __restrict__ B,
    const float* __restrict__ bias, float* __restrict__ C,
    int M, int N, int Kd, int mode, const float* __restrict__ res)
{
    __shared__ float As[16][64];
    __shared__ float Bs[16][64];
    int t  = threadIdx.x;
    int n0 = blockIdx.x * 64, m0 = blockIdx.y * 64;
    int tx = t & 15, ty = t >> 4;
    float acc[4][4] = {};
    int arow = t >> 2, ak = (t & 3) * 4;
    int bk   = t >> 4, bn = (t & 15) * 4;

    for (int k0 = 0; k0 < Kd; k0 += 16) {
        float4 av = *(const float4*)&A[(size_t)(m0 + arow)*Kd + k0 + ak];
        As[ak+0][arow] = av.x; As[ak+1][arow] = av.y;
        As[ak+2][arow] = av.z; As[ak+3][arow] = av.w;
        *(float4*)&Bs[bk][bn] = *(const float4*)&B[(size_t)(k0 + bk)*N + n0 + bn];
        __syncthreads();
        #pragma unroll
        for (int kk = 0; kk < 16; kk++) {
            float4 a4 = *(const float4*)&As[kk][ty*4];
            float4 b4 = *(const float4*)&Bs[kk][tx*4];
            float aa[4] = {a4.x, a4.y, a4.z, a4.w};
            float bb[4] = {b4.x, b4.y, b4.z, b4.w};
            #pragma unroll
            for (int i = 0; i < 4; i++)
                #pragma unroll
                for (int j = 0; j < 4; j++)
                    acc[i][j] += aa[i] * bb[j];
        }
        __syncthreads();
    }

    #pragma unroll
    for (int i = 0; i < 4; i++) {
        int m = m0 + ty*4 + i;
        float mask = 1.0f;
        if (mode == 2 || mode == 3) mask = (g_cnt[m] > 0) ? 1.0f : 0.0f;
        #pragma unroll
        for (int j = 0; j < 4; j++) {
            int n = n0 + tx*4 + j;
            float v = acc[i][j] + bias[n];
            if      (mode == 1) v = phif(v);
            else if (mode == 2) v = phif(v) * mask;
            else if (mode == 3) v = v * mask;
            else if (mode == 4) v = v + res[(size_t)m*N + n];
            else if (mode == 5) v = geluf(v);
            C[(size_t)m*N + n] = v;
        }
    }
}

__global__ __launch_bounds__(256) void k_kvsum() {
    int b = blockIdx.x;
    int s = b >> 2, h = b & 3;
    int t = threadIdx.x, tx = t & 15, ty = t >> 4;
    __shared__ float ks[8][64], vs[8][64];
    float acc[4][4] = {};
    float ksl = 0.0f;
    const float* kp = g_k + ((size_t)s*KK*NHH + h)*HDD;
    const float* vp = g_v + ((size_t)s*KK*NHH + h)*HDD;

    for (int k0 = 0; k0 < KK; k0 += 8) {
        #pragma unroll
        for (int u = 0; u < 2; u++) {
            int idx = t + u*256; int i = idx >> 6, d = idx & 63;
            ks[i][d] = kp[(size_t)(k0 + i)*NHH*HDD + d];
            vs[i][d] = vp[(size_t)(k0 + i)*NHH*HDD + d];
        }
        __syncthreads();
        if (t < 64) {
            #pragma unroll
            for (int i = 0; i < 8; i++) ksl += ks[i][t];
        }
        #pragma unroll
        for (int i = 0; i < 8; i++) {
            float kd[4], ve[4];
            #pragma unroll
            for (int j = 0; j < 4; j++) { kd[j] = ks[i][ty*4+j]; ve[j] = vs[i][tx*4+j]; }
            #pragma unroll
            for (int a = 0; a < 4; a++)
                #pragma unroll
                for (int c = 0; c < 4; c++)
                    acc[a][c] += kd[a] * ve[c];
        }
        __syncthreads();
    }
    if (t < 64) g_ksum[(size_t)b*64 + t] = ksl;
    #pragma unroll
    for (int a = 0; a < 4; a++)
        #pragma unroll
        for (int c = 0; c < 4; c++)
            g_kv[((size_t)b*64 + ty*4 + a)*64 + tx*4 + c] = acc[a][c];
}

__global__ void k_attn() {
    int r = blockIdx.x;
    int s = r / KK;
    int t = threadIdx.x;
    __shared__ float qs[256];
    qs[t] = g_q[(size_t)r*DD + t];
    __syncthreads();
    int h = t >> 6, e = t & 63;
    const float* kvp = g_kv   + (size_t)(s*NHH + h)*HDD*HDD;
    const float* ksp = g_ksum + (size_t)(s*NHH + h)*HDD;
    float num = 0.f, den = 0.f;
    #pragma unroll 8
    for (int d = 0; d < 64; d++) {
        float q = qs[h*64 + d];
        num += q * kvp[d*64 + e];
        den += q * ksp[d];
    }
    g_attn[(size_t)r*DD + t] = num / (den + 1e-6f);
}

// ---- big GEMM via mma.sync bf16x3: C[M,256] = epi(A[M,256] @ Bt^T) ----
// Bt stored [n][k] (hi/lo). Tile: CTA 128x128, warp 32x64, K-chunk 32.
// mode 1: C = gelu(acc + p2[(s*KK+pid[m])*256 + col])
// mode 2: C = acc + bias[col] + res[m*256+col]
__global__ __launch_bounds__(256, 2) void k_mma(
    const float* __restrict__ A,
    const __nv_bfloat16* __restrict__ Bh,
    const __nv_bfloat16* __restrict__ Bl,
    float* __restrict__ C, int mode,
    const float* __restrict__ p2, const int* __restrict__ pid,
    const float* __restrict__ bias, const float* __restrict__ res)
{
    __shared__ __nv_bfloat16 Ash[128][40];   // 32 cols + pad (80B row stride)
    __shared__ __nv_bfloat16 Asl[128][40];
    __shared__ __nv_bfloat16 Bsh[128][40];
    __shared__ __nv_bfloat16 Bsl[128][40];

    const int t = threadIdx.x, lane = t & 31, wid = t >> 5;
    const int n0 = blockIdx.x * 128, m0 = blockIdx.y * 128;
    const int wm = (wid & 3) * 32;      // warp M offset in tile
    const int wn = (wid >> 2) * 64;     // warp N offset in tile

    const uint32_t sAh = smem_u32(Ash), sAl = smem_u32(Asl);
    const uint32_t sBh = smem_u32(Bsh), sBl = smem_u32(Bsl);

    // precompute per-lane ldmatrix offsets (element indices; *2 for bytes)
    const int a_m = wm + (lane & 15);
    const int a_k = (lane >> 4) << 3;                       // +8 for upper half
    const int b_n = wn + ((lane >> 4) << 3) + (lane & 7);   // within n16 group
    const int b_k = ((lane >> 3) & 1) << 3;

    float acc[2][8][4] = {};

    for (int c = 0; c < 8; c++) {
        const int k0 = c * 32;
        // A: 128x32 fp32 -> bf16 hi/lo. 1024 float4 loads over 256 threads.
        #pragma unroll
        for (int i = 0; i < 4; i++) {
            int lin = t + 256 * i;
            int row = lin >> 3, q = lin & 7;
            float4 f = *(const float4*)(A + (size_t)(m0 + row)*DD + k0 + q*4);
            uint32_t h01 = pack_bf2(f.x, f.y);
            uint32_t h23 = pack_bf2(f.z, f.w);
            uint32_t l01 = pack_bf2(f.x - bflo(h01), f.y - bfhi(h01));
            uint32_t l23 = pack_bf2(f.z - bflo(h23), f.w - bfhi(h23));
            *(uint2*)&Ash[row][q*4] = make_uint2(h01, h23);
            *(uint2*)&Asl[row][q*4] = make_uint2(l01, l23);
        }
        // B: 128x32 bf16 (hi+lo). 512 uint4 loads per array.
        #pragma unroll
        for (int i = 0; i < 2; i++) {
            int lin = t + 256 * i;
            int row = lin >> 2, q = lin & 3;
            *(uint4*)&Bsh[row][q*8] = *(const uint4*)(Bh + (size_t)(n0 + row)*DD + k0 + q*8);
            *(uint4*)&Bsl[row][q*8] = *(const uint4*)(Bl + (size_t)(n0 + row)*DD + k0 + q*8);
        }
        __syncthreads();

        #pragma unroll
        for (int kk = 0; kk < 2; kk++) {
            uint32_t ah[2][4], al[2][4];
            #pragma unroll
            for (int mt = 0; mt < 2; mt++) {
                uint32_t offA = (uint32_t)((a_m + mt*16) * 40 + kk*16 + a_k) * 2;
                LDSM_X4(ah[mt][0], ah[mt][1], ah[mt][2], ah[mt][3], sAh + offA);
                LDSM_X4(al[mt][0], al[mt][1], al[mt][2], al[mt][3], sAl + offA);
            }
            #pragma unroll
            for (int g = 0; g < 4; g++) {
                uint32_t offB = (uint32_t)((b_n + g*16) * 40 + kk*16 + b_k) * 2;
                uint32_t bh[2][2], bl[2][2];
                LDSM_X4(bh[0][0], bh[0][1], bh[1][0], bh[1][1], sBh + offB);
                LDSM_X4(bl[0][0], bl[0][1], bl[1][0], bl[1][1], sBl + offB);
                #pragma unroll
                for (int mt = 0; mt < 2; mt++) {
                    #pragma unroll
                    for (int j = 0; j < 2; j++) {
                        float* d = acc[mt][g*2 + j];
                        MMA_BF16(d, ah[mt], bh[j]);
                        MMA_BF16(d, ah[mt], bl[j]);
                        MMA_BF16(d, al[mt], bh[j]);
                    }
                }
            }
        }
        __syncthreads();
    }

    // epilogue: acc[mt][nt][0..1] -> row lr, cols lc..lc+1; [2..3] -> row lr+8
    const int lr = lane >> 2;
    const int lc = (lane & 3) * 2;
    #pragma unroll
    for (int mt = 0; mt < 2; mt++) {
        int mrow0 = m0 + wm + mt*16 + lr;
        int mrow1 = mrow0 + 8;
        if (mode == 1) {
            int s = mrow0 >> 15;
            const float* p2r0 = p2 + ((size_t)(s*KK + pid[mrow0]))*DD;
            const float* p2r1 = p2 + ((size_t)(s*KK + pid[mrow1]))*DD;
            #pragma unroll
            for (int nt = 0; nt < 8; nt++) {
                int col = n0 + wn + nt*8 + lc;
                float2 o0, o1;
                o0.x = geluf(acc[mt][nt][0] + p2r0[col]);
                o0.y = geluf(acc[mt][nt][1] + p2r0[col+1]);
                o1.x = geluf(acc[mt][nt][2] + p2r1[col]);
                o1.y = geluf(acc[mt][nt][3] + p2r1[col+1]);
                *(float2*)(C + (size_t)mrow0*DD + col) = o0;
                *(float2*)(C + (size_t)mrow1*DD + col) = o1;
            }
        } else {
            #pragma unroll
            for (int nt = 0; nt < 8; nt++) {
                int col = n0 + wn + nt*8 + lc;
                float2 bv = *(const float2*)(bias + col);
                float2 r0 = *(const float2*)(res + (size_t)mrow0*DD + col);
                float2 r1 = *(const float2*)(res + (size_t)mrow1*DD + col);
                float2 o0, o1;
                o0.x = acc[mt][nt][0] + bv.x + r0.x;
                o0.y = acc[mt][nt][1] + bv.y + r0.y;
                o1.x = acc[mt][nt][2] + bv.x + r1.x;
                o1.y = acc[mt][nt][3] + bv.y + r1.y;
                *(float2*)(C + (size_t)mrow0*DD + col) = o0;
                *(float2*)(C + (size_t)mrow1*DD + col) = o1;
            }
        }
    }
}

// ---------------- launch ----------------
extern "C" void kernel_launch(void* const* d_in, const int* in_sizes, int n_in,
                              void* d_out, int out_size) {
    (void)in_sizes; (void)n_in; (void)out_size;
    const float* H    = (const float*)d_in[0];
    const int*   pid  = (const int*)  d_in[1];
    const float* ln1g = (const float*)d_in[2];
    const float* ln1b = (const float*)d_in[3];
    const float* Wq   = (const float*)d_in[4];
    const float* bq   = (const float*)d_in[5];
    const float* Wk   = (const float*)d_in[6];
    const float* bk   = (const float*)d_in[7];
    const float* Wv   = (const float*)d_in[8];
    const float* bv   = (const float*)d_in[9];
    const float* Wo   = (const float*)d_in[10];
    const float* bo   = (const float*)d_in[11];
    const float* ln2g = (const float*)d_in[12];
    const float* ln2b = (const float*)d_in[13];
    const float* fW1  = (const float*)d_in[14];
    const float* fb1  = (const float*)d_in[15];
    const float* fW2  = (const float*)d_in[16];
    const float* fb2  = (const float*)d_in[17];
    const float* mW1  = (const float*)d_in[18];
    const float* mb1  = (const float*)d_in[19];
    const float* mW2  = (const float*)d_in[20];
    const float* mb2  = (const float*)d_in[21];

    float* out = (float*)d_out;
    float* psu = out + (size_t)SS*NN*DD;

    float *p_x, *p_y, *p_q, *p_k, *p_v, *p_attn, *p_x2, *p_h, *p_p2, *p_hid;
    __nv_bfloat16 *p_w1h, *p_w1l, *p_w2h, *p_w2l;
    cudaGetSymbolAddress((void**)&p_x,    g_x);
    cudaGetSymbolAddress((void**)&p_y,    g_y);
    cudaGetSymbolAddress((void**)&p_q,    g_q);
    cudaGetSymbolAddress((void**)&p_k,    g_k);
    cudaGetSymbolAddress((void**)&p_v,    g_v);
    cudaGetSymbolAddress((void**)&p_attn, g_attn);
    cudaGetSymbolAddress((void**)&p_x2,   g_x2);
    cudaGetSymbolAddress((void**)&p_h,    g_h);
    cudaGetSymbolAddress((void**)&p_p2,   g_p2);
    cudaGetSymbolAddress((void**)&p_hid,  g_hid);
    cudaGetSymbolAddress((void**)&p_w1h,  g_w1h);
    cudaGetSymbolAddress((void**)&p_w1l,  g_w1l);
    cudaGetSymbolAddress((void**)&p_w2h,  g_w2h);
    cudaGetSymbolAddress((void**)&p_w2l,  g_w2l);

    // 1) pooling + weight prep
    k_zero<<<(SS*KK*DD + 255)/256, 256>>>();
    k_prep_w<<<256, 256>>>(mW1, mW2);
    k_pool<<<SS*NN, 256>>>(H, pid);
    k_finalize<<<SS*KK, 256>>>();

    // 2) patch transformer
    k_ln<<<SS*KK, 256>>>(p_x, ln1g, ln1b, p_y);
    dim3 g64(DD/64, (SS*KK)/64);
    k_gemm64<<<g64, 256>>>(p_y, Wq, bq, p_q, SS*KK, DD, DD, 1, nullptr);
    k_gemm64<<<g64, 256>>>(p_y, Wk, bk, p_k, SS*KK, DD, DD, 2, nullptr);
    k_gemm64<<<g64, 256>>>(p_y, Wv, bv, p_v, SS*KK, DD, DD, 3, nullptr);
    k_kvsum<<<SS*NHH, 256>>>();
    k_attn<<<SS*KK, 256>>>();
    k_gemm64<<<g64, 256>>>(p_attn, Wo, bo, p_x2, SS*KK, DD, DD, 4, p_x);
    k_ln<<<SS*KK, 256>>>(p_x2, ln2g, ln2b, p_y);
    dim3 gf1(FF/64, (SS*KK)/64);
    k_gemm64<<<gf1, 256>>>(p_y, fW1, fb1, p_h, SS*KK, FF, DD, 5, nullptr);
    k_gemm64<<<g64, 256>>>(p_h, fW2, fb2, psu, SS*KK, DD, FF, 4, p_x2);

    // 3) node MLP via tensor cores (mma.sync bf16x3)
    k_gemm64<<<g64, 256>>>(psu, mW1 + DD*DD, mb1, p_p2, SS*KK, DD, DD, 0, nullptr);
    dim3 gb(DD/128, (SS*NN)/128);   // (2, 1024)
    k_mma<<<gb, 256>>>(H,     p_w1h, p_w1l, p_hid, 1, p_p2, pid, nullptr, nullptr);
    k_mma<<<gb, 256>>>(p_hid, p_w2h, p_w2l, out,   2, nullptr, nullptr, mb2, H);
}

// round 5
// speedup vs baseline: 1.8329x; 1.0875x over previous
#include <cuda_runtime.h>
#include <cuda_bf16.h>
#include <math.h>
#include <stdint.h>

// Problem constants
#define SS  4
#define NN  32768
#define DD  256
#define KK  512
#define NHH 4
#define HDD 64
#define FF  1024
#define QKVW 768

// ---------------- scratch (device globals; no runtime allocation) ----------------
__device__ float g_x   [SS*KK*DD];
__device__ int   g_cnt [SS*KK];
__device__ int   g_off [SS*KK];
__device__ int   g_cur [SS*KK];
__device__ int   g_nlist[SS*NN];
__device__ float g_y   [SS*KK*DD];
__device__ float g_qkv [SS*KK*QKVW];
__device__ float g_kv  [SS*NHH*HDD*HDD];
__device__ float g_ksum[SS*NHH*HDD];
__device__ float g_attn[SS*KK*DD];
__device__ float g_x2  [SS*KK*DD];
__device__ float g_h   [SS*KK*FF];
__device__ float g_p2  [SS*KK*DD];
__device__ float g_hid [SS*NN*DD];          // node MLP hidden (fp32)
__device__ float g_wqkv[DD*QKVW];           // [k][Wq|Wk|Wv]
__device__ float g_bqkv[QKVW];
__device__ __nv_bfloat16 g_w1h[DD*DD];      // W1a^T hi  [n][k]
__device__ __nv_bfloat16 g_w1l[DD*DD];      // W1a^T lo
__device__ __nv_bfloat16 g_w2h[DD*DD];      // W2^T hi
__device__ __nv_bfloat16 g_w2l[DD*DD];      // W2^T lo

// ---------------- small device helpers ----------------
__device__ __forceinline__ float geluf(float x) {
    return 0.5f * x * (1.0f + erff(x * 0.70710678118654752440f));
}
__device__ __forceinline__ float phif(float x) {   // elu(x)+1
    return x > 0.0f ? x + 1.0f : expf(x);
}
__device__ __forceinline__ uint32_t pack_bf2(float a, float b) {
    __nv_bfloat162 t = __floats2bfloat162_rn(a, b);
    return *(uint32_t*)&t;
}
__device__ __forceinline__ float bflo(uint32_t p) {
    __nv_bfloat162 b = *(__nv_bfloat162*)&p; return __bfloat162float(b.x);
}
__device__ __forceinline__ float bfhi(uint32_t p) {
    __nv_bfloat162 b = *(__nv_bfloat162*)&p; return __bfloat162float(b.y);
}
__device__ __forceinline__ uint32_t smem_u32(const void* p) {
    uint32_t a;
    asm("{ .reg .u64 t; cvta.to.shared.u64 t, %1; cvt.u32.u64 %0, t; }" : "=r"(a) : "l"(p));
    return a;
}
#define LDSM_X4(r0, r1, r2, r3, addr) \
    asm volatile("ldmatrix.sync.aligned.m8n8.x4.shared.b16 {%0,%1,%2,%3}, [%4];" \
                 : "=r"(r0), "=r"(r1), "=r"(r2), "=r"(r3) : "r"(addr))
#define MMA_BF16(d, a, b) \
    asm volatile("mma.sync.aligned.m16n8k16.row.col.f32.bf16.bf16.f32 " \
                 "{%0,%1,%2,%3},{%4,%5,%6,%7},{%8,%9},{%0,%1,%2,%3};" \
                 : "+f"((d)[0]), "+f"((d)[1]), "+f"((d)[2]), "+f"((d)[3]) \
                 : "r"((a)[0]), "r"((a)[1]), "r"((a)[2]), "r"((a)[3]), \
                   "r"((b)[0]), "r"((b)[1]))

// ---------------- pooling (count-sort, no fp32 atomics) ----------------
__global__ void k_zero_cnt() {
    int i = blockIdx.x * blockDim.x + threadIdx.x;
    if (i < SS*KK) g_cnt[i] = 0;
}

__global__ void k_count(const int* __restrict__ pid) {
    int b = blockIdx.x * blockDim.x + threadIdx.x;   // node
    int s = b >> 15;
    atomicAdd(&g_cnt[s*KK + pid[b]], 1);
}

// exclusive prefix scan over 2048 counts; 256 threads, 8 values each
__global__ void k_scan() {
    __shared__ int part[256];
    int t = threadIdx.x;
    int base = t * 8;
    int loc[8];
    int sum = 0;
    #pragma unroll
    for (int i = 0; i < 8; i++) { loc[i] = sum; sum += g_cnt[base + i]; }
    part[t] = sum;
    __syncthreads();
    #pragma unroll
    for (int off = 1; off < 256; off <<= 1) {
        int v = (t >= off) ? part[t - off] : 0;
        __syncthreads();
        part[t] += v;
        __syncthreads();
    }
    int prev = (t > 0) ? part[t - 1] : 0;
    #pragma unroll
    for (int i = 0; i < 8; i++) {
        g_off[base + i] = prev + loc[i];
        g_cur[base + i] = prev + loc[i];
    }
}

__global__ void k_scatter(const int* __restrict__ pid) {
    int b = blockIdx.x * blockDim.x + threadIdx.x;
    int s = b >> 15;
    int pos = atomicAdd(&g_cur[s*KK + pid[b]], 1);
    g_nlist[pos] = b;
}

// one block per patch: coalesced segmented mean
__global__ __launch_bounds__(256) void k_patchsum(const float* __restrict__ H) {
    int r = blockIdx.x;            // global patch
    int d = threadIdx.x;
    int cnt = g_cnt[r];
    int off = g_off[r];
    float a0 = 0.f, a1 = 0.f, a2 = 0.f, a3 = 0.f;
    int i = 0;
    for (; i + 4 <= cnt; i += 4) {
        int n0 = g_nlist[off+i],   n1 = g_nlist[off+i+1];
        int n2 = g_nlist[off+i+2], n3 = g_nlist[off+i+3];
        a0 += __ldg(&H[(size_t)n0*DD + d]);
        a1 += __ldg(&H[(size_t)n1*DD + d]);
        a2 += __ldg(&H[(size_t)n2*DD + d]);
        a3 += __ldg(&H[(size_t)n3*DD + d]);
    }
    for (; i < cnt; i++) a0 += __ldg(&H[(size_t)g_nlist[off+i]*DD + d]);
    float sum = (a0 + a1) + (a2 + a3);
    float inv = (cnt > 0) ? (1.0f / (float)cnt) : 0.0f;
    g_x[(size_t)r*DD + d] = sum * inv;
}

// ---------------- weight prep: bf16 split + qkv concat ----------------
__global__ void k_prep_w(const float* __restrict__ W1, const float* __restrict__ W2,
                         const float* __restrict__ Wq, const float* __restrict__ Wk,
                         const float* __restrict__ Wv, const float* __restrict__ bq,
                         const float* __restrict__ bk, const float* __restrict__ bv) {
    int n = blockIdx.x, k = threadIdx.x;
    float v1 = W1[k*DD + n];
    __nv_bfloat16 h1 = __float2bfloat16(v1);
    g_w1h[n*DD + k] = h1;
    g_w1l[n*DD + k] = __float2bfloat16(v1 - __bfloat162float(h1));
    float v2 = W2[k*DD + n];
    __nv_bfloat16 h2 = __float2bfloat16(v2);
    g_w2h[n*DD + k] = h2;
    g_w2l[n*DD + k] = __float2bfloat16(v2 - __bfloat162float(h2));
    g_wqkv[k*QKVW + n]       = Wq[k*DD + n];
    g_wqkv[k*QKVW + 256 + n] = Wk[k*DD + n];
    g_wqkv[k*QKVW + 512 + n] = Wv[k*DD + n];
    if (n == 0) {
        g_bqkv[k] = bq[k]; g_bqkv[256 + k] = bk[k]; g_bqkv[512 + k] = bv[k];
    }
}

// ---------------- layer norm ----------------
__global__ void k_ln(const float* __restrict__ in, const float* __restrict__ gw,
                     const float* __restrict__ bw, float* __restrict__ out) {
    int r = blockIdx.x, d = threadIdx.x;
    float v = in[(size_t)r*DD + d];
    __shared__ float s1[8], s2[8];
    __shared__ float smu, sri;
    float a = v, b = v * v;
    #pragma unroll
    for (int o = 16; o > 0; o >>= 1) {
        a += __shfl_down_sync(0xffffffffu, a, o);
        b += __shfl_down_sync(0xffffffffu, b, o);
    }
    if ((d & 31) == 0) { s1[d >> 5] = a; s2[d >> 5] = b; }
    __syncthreads();
    if (d == 0) {
        float sa = 0.f, sb = 0.f;
        #pragma unroll
        for (int i = 0; i < 8; i++) { sa += s1[i]; sb += s2[i]; }
        float m   = sa * (1.0f / DD);
        float var = sb * (1.0f / DD) - m * m;
        smu = m; sri = rsqrtf(var + 1e-5f);
    }
    __syncthreads();
    out[(size_t)r*DD + d] = (v - smu) * sri * gw[d] + bw[d];
}

// 64x64 tiled SGEMM for patch-level ops.
// modes: 0=+bias; 4=+res; 5=gelu; 6=qkv (col<256 phi, <512 phi*mask, else *mask)
__global__ __launch_bounds__(256) void k_gemm64(
    const float* __restrict__ A, const float* __restrict__ B,
    const float* __restrict__ bias, float* __restrict__ C,
    int M, int N, int Kd, int mode, const float* __restrict__ res)
{
    __shared__ float As[16][64];
    __shared__ float Bs[16][64];
    int t  = threadIdx.x;
    int n0 = blockIdx.x * 64, m0 = blockIdx.y * 64;
    int tx = t & 15, ty = t >> 4;
    float acc[4][4] = {};
    int arow = t >> 2, ak = (t & 3) * 4;
    int bk   = t >> 4, bn = (t & 15) * 4;

    for (int k0 = 0; k0 < Kd; k0 += 16) {
        float4 av = *(const float4*)&A[(size_t)(m0 + arow)*Kd + k0 + ak];
        As[ak+0][arow] = av.x; As[ak+1][arow] = av.y;
        As[ak+2][arow] = av.z; As[ak+3][arow] = av.w;
        *(float4*)&Bs[bk][bn] = *(const float4*)&B[(size_t)(k0 + bk)*N + n0 + bn];
        __syncthreads();
        #pragma unroll
        for (int kk = 0; kk < 16; kk++) {
            float4 a4 = *(const float4*)&As[kk][ty*4];
            float4 b4 = *(const float4*)&Bs[kk][tx*4];
            float aa[4] = {a4.x, a4.y, a4.z, a4.w};
            float bb[4] = {b4.x, b4.y, b4.z, b4.w};
            #pragma unroll
            for (int i = 0; i < 4; i++)
                #pragma unroll
                for (int j = 0; j < 4; j++)
                    acc[i][j] += aa[i] * bb[j];
        }
        __syncthreads();
    }

    #pragma unroll
    for (int i = 0; i < 4; i++) {
        int m = m0 + ty*4 + i;
        float mask = (mode == 6) ? ((g_cnt[m] > 0) ? 1.0f : 0.0f) : 1.0f;
        #pragma unroll
        for (int j = 0; j < 4; j++) {
            int n = n0 + tx*4 + j;
            float v = acc[i][j] + bias[n];
            if      (mode == 4) v = v + res[(size_t)m*N + n];
            else if (mode == 5) v = geluf(v);
            else if (mode == 6) {
                if      (n < 256) v = phif(v);
                else if (n < 512) v = phif(v) * mask;
                else              v = v * mask;
            }
            C[(size_t)m*N + n] = v;
        }
    }
}

// kv[s,h,d,e] = sum_k k[s,k,h,d]*v[s,k,h,e];  ksum from g_qkv (stride 768)
__global__ __launch_bounds__(256) void k_kvsum() {
    int b = blockIdx.x;
    int s = b >> 2, h = b & 3;
    int t = threadIdx.x, tx = t & 15, ty = t >> 4;
    __shared__ float ks[8][64], vs[8][64];
    float acc[4][4] = {};
    float ksl = 0.0f;
    const float* kp = g_qkv + (size_t)s*KK*QKVW + 256 + h*HDD;
    const float* vp = g_qkv + (size_t)s*KK*QKVW + 512 + h*HDD;

    for (int k0 = 0; k0 < KK; k0 += 8) {
        #pragma unroll
        for (int u = 0; u < 2; u++) {
            int idx = t + u*256; int i = idx >> 6, d = idx & 63;
            ks[i][d] = kp[(size_t)(k0 + i)*QKVW + d];
            vs[i][d] = vp[(size_t)(k0 + i)*QKVW + d];
        }
        __syncthreads();
        if (t < 64) {
            #pragma unroll
            for (int i = 0; i < 8; i++) ksl += ks[i][t];
        }
        #pragma unroll
        for (int i = 0; i < 8; i++) {
            float kd[4], ve[4];
            #pragma unroll
            for (int j = 0; j < 4; j++) { kd[j] = ks[i][ty*4+j]; ve[j] = vs[i][tx*4+j]; }
            #pragma unroll
            for (int a = 0; a < 4; a++)
                #pragma unroll
                for (int c = 0; c < 4; c++)
                    acc[a][c] += kd[a] * ve[c];
        }
        __syncthreads();
    }
    if (t < 64) g_ksum[(size_t)b*64 + t] = ksl;
    #pragma unroll
    for (int a = 0; a < 4; a++)
        #pragma unroll
        for (int c = 0; c < 4; c++)
            g_kv[((size_t)b*64 + ty*4 + a)*64 + tx*4 + c] = acc[a][c];
}

__global__ void k_attn() {
    int r = blockIdx.x;
    int s = r / KK;
    int t = threadIdx.x;
    __shared__ float qs[256];
    qs[t] = g_qkv[(size_t)r*QKVW + t];
    __syncthreads();
    int h = t >> 6, e = t & 63;
    const float* kvp = g_kv   + (size_t)(s*NHH + h)*HDD*HDD;
    const float* ksp = g_ksum + (size_t)(s*NHH + h)*HDD;
    float num = 0.f, den = 0.f;
    #pragma unroll 8
    for (int d = 0; d < 64; d++) {
        float q = qs[h*64 + d];
        num += q * kvp[d*64 + e];
        den += q * ksp[d];
    }
    g_attn[(size_t)r*DD + t] = num / (den + 1e-6f);
}

// ---- big GEMM via mma.sync bf16x3: C[M,256] = epi(A[M,256] @ Bt^T) ----
// mode 1: C = gelu(acc + p2[(s*KK+pid[m])*256 + col])
// mode 2: C = acc + bias[col] + res[m*256+col]
__global__ __launch_bounds__(256, 2) void k_mma(
    const float* __restrict__ A,
    const __nv_bfloat16* __restrict__ Bh,
    const __nv_bfloat16* __restrict__ Bl,
    float* __restrict__ C, int mode,
    const float* __restrict__ p2, const int* __restrict__ pid,
    const float* __restrict__ bias, const float* __restrict__ res)
{
    __shared__ __nv_bfloat16 Ash[128][40];
    __shared__ __nv_bfloat16 Asl[128][40];
    __shared__ __nv_bfloat16 Bsh[128][40];
    __shared__ __nv_bfloat16 Bsl[128][40];

    const int t = threadIdx.x, lane = t & 31, wid = t >> 5;
    const int n0 = blockIdx.x * 128, m0 = blockIdx.y * 128;
    const int wm = (wid & 3) * 32;
    const int wn = (wid >> 2) * 64;

    const uint32_t sAh = smem_u32(Ash), sAl = smem_u32(Asl);
    const uint32_t sBh = smem_u32(Bsh), sBl = smem_u32(Bsl);

    const int a_m = wm + (lane & 15);
    const int a_k = (lane >> 4) << 3;
    const int b_n = wn + ((lane >> 4) << 3) + (lane & 7);
    const int b_k = ((lane >> 3) & 1) << 3;

    float acc[2][8][4] = {};

    for (int c = 0; c < 8; c++) {
        const int k0 = c * 32;
        #pragma unroll
        for (int i = 0; i < 4; i++) {
            int lin = t + 256 * i;
            int row = lin >> 3, q = lin & 7;
            float4 f = *(const float4*)(A + (size_t)(m0 + row)*DD + k0 + q*4);
            uint32_t h01 = pack_bf2(f.x, f.y);
            uint32_t h23 = pack_bf2(f.z, f.w);
            uint32_t l01 = pack_bf2(f.x - bflo(h01), f.y - bfhi(h01));
            uint32_t l23 = pack_bf2(f.z - bflo(h23), f.w - bfhi(h23));
            *(uint2*)&Ash[row][q*4] = make_uint2(h01, h23);
            *(uint2*)&Asl[row][q*4] = make_uint2(l01, l23);
        }
        #pragma unroll
        for (int i = 0; i < 2; i++) {
            int lin = t + 256 * i;
            int row = lin >> 2, q = lin & 3;
            *(uint4*)&Bsh[row][q*8] = *(const uint4*)(Bh + (size_t)(n0 + row)*DD + k0 + q*8);
            *(uint4*)&Bsl[row][q*8] = *(const uint4*)(Bl + (size_t)(n0 + row)*DD + k0 + q*8);
        }
        __syncthreads();

        #pragma unroll
        for (int kk = 0; kk < 2; kk++) {
            uint32_t ah[2][4], al[2][4];
            #pragma unroll
            for (int mt = 0; mt < 2; mt++) {
                uint32_t offA = (uint32_t)((a_m + mt*16) * 40 + kk*16 + a_k) * 2;
                LDSM_X4(ah[mt][0], ah[mt][1], ah[mt][2], ah[mt][3], sAh + offA);
                LDSM_X4(al[mt][0], al[mt][1], al[mt][2], al[mt][3], sAl + offA);
            }
            #pragma unroll
            for (int g = 0; g < 4; g++) {
                uint32_t offB = (uint32_t)((b_n + g*16) * 40 + kk*16 + b_k) * 2;
                uint32_t bh[2][2], bl[2][2];
                LDSM_X4(bh[0][0], bh[0][1], bh[1][0], bh[1][1], sBh + offB);
                LDSM_X4(bl[0][0], bl[0][1], bl[1][0], bl[1][1], sBl + offB);
                #pragma unroll
                for (int mt = 0; mt < 2; mt++) {
                    #pragma unroll
                    for (int j = 0; j < 2; j++) {
                        float* d = acc[mt][g*2 + j];
                        MMA_BF16(d, ah[mt], bh[j]);
                        MMA_BF16(d, ah[mt], bl[j]);
                        MMA_BF16(d, al[mt], bh[j]);
                    }
                }
            }
        }
        __syncthreads();
    }

    const int lr = lane >> 2;
    const int lc = (lane & 3) * 2;
    #pragma unroll
    for (int mt = 0; mt < 2; mt++) {
        int mrow0 = m0 + wm + mt*16 + lr;
        int mrow1 = mrow0 + 8;
        if (mode == 1) {
            int s = mrow0 >> 15;
            const float* p2r0 = p2 + ((size_t)(s*KK + pid[mrow0]))*DD;
            const float* p2r1 = p2 + ((size_t)(s*KK + pid[mrow1]))*DD;
            #pragma unroll
            for (int nt = 0; nt < 8; nt++) {
                int col = n0 + wn + nt*8 + lc;
                float2 o0, o1;
                o0.x = geluf(acc[mt][nt][0] + p2r0[col]);
                o0.y = geluf(acc[mt][nt][1] + p2r0[col+1]);
                o1.x = geluf(acc[mt][nt][2] + p2r1[col]);
                o1.y = geluf(acc[mt][nt][3] + p2r1[col+1]);
                *(float2*)(C + (size_t)mrow0*DD + col) = o0;
                *(float2*)(C + (size_t)mrow1*DD + col) = o1;
            }
        } else {
            #pragma unroll
            for (int nt = 0; nt < 8; nt++) {
                int col = n0 + wn + nt*8 + lc;
                float2 bv = *(const float2*)(bias + col);
                float2 r0 = *(const float2*)(res + (size_t)mrow0*DD + col);
                float2 r1 = *(const float2*)(res + (size_t)mrow1*DD + col);
                float2 o0, o1;
                o0.x = acc[mt][nt][0] + bv.x + r0.x;
                o0.y = acc[mt][nt][1] + bv.y + r0.y;
                o1.x = acc[mt][nt][2] + bv.x + r1.x;
                o1.y = acc[mt][nt][3] + bv.y + r1.y;
                *(float2*)(C + (size_t)mrow0*DD + col) = o0;
                *(float2*)(C + (size_t)mrow1*DD + col) = o1;
            }
        }
    }
}

// ---------------- launch ----------------
extern "C" void kernel_launch(void* const* d_in, const int* in_sizes, int n_in,
                              void* d_out, int out_size) {
    (void)in_sizes; (void)n_in; (void)out_size;
    const float* H    = (const float*)d_in[0];
    const int*   pid  = (const int*)  d_in[1];
    const float* ln1g = (const float*)d_in[2];
    const float* ln1b = (const float*)d_in[3];
    const float* Wq   = (const float*)d_in[4];
    const float* bq   = (const float*)d_in[5];
    const float* Wk   = (const float*)d_in[6];
    const float* bk   = (const float*)d_in[7];
    const float* Wv   = (const float*)d_in[8];
    const float* bv   = (const float*)d_in[9];
    const float* Wo   = (const float*)d_in[10];
    const float* bo   = (const float*)d_in[11];
    const float* ln2g = (const float*)d_in[12];
    const float* ln2b = (const float*)d_in[13];
    const float* fW1  = (const float*)d_in[14];
    const float* fb1  = (const float*)d_in[15];
    const float* fW2  = (const float*)d_in[16];
    const float* fb2  = (const float*)d_in[17];
    const float* mW1  = (const float*)d_in[18];
    const float* mb1  = (const float*)d_in[19];
    const float* mW2  = (const float*)d_in[20];
    const float* mb2  = (const float*)d_in[21];

    float* out = (float*)d_out;
    float* psu = out + (size_t)SS*NN*DD;

    float *p_x, *p_y, *p_qkv, *p_attn, *p_x2, *p_h, *p_p2, *p_hid, *p_wqkv, *p_bqkv;
    __nv_bfloat16 *p_w1h, *p_w1l, *p_w2h, *p_w2l;
    cudaGetSymbolAddress((void**)&p_x,    g_x);
    cudaGetSymbolAddress((void**)&p_y,    g_y);
    cudaGetSymbolAddress((void**)&p_qkv,  g_qkv);
    cudaGetSymbolAddress((void**)&p_attn, g_attn);
    cudaGetSymbolAddress((void**)&p_x2,   g_x2);
    cudaGetSymbolAddress((void**)&p_h,    g_h);
    cudaGetSymbolAddress((void**)&p_p2,   g_p2);
    cudaGetSymbolAddress((void**)&p_hid,  g_hid);
    cudaGetSymbolAddress((void**)&p_wqkv, g_wqkv);
    cudaGetSymbolAddress((void**)&p_bqkv, g_bqkv);
    cudaGetSymbolAddress((void**)&p_w1h,  g_w1h);
    cudaGetSymbolAddress((void**)&p_w1l,  g_w1l);
    cudaGetSymbolAddress((void**)&p_w2h,  g_w2h);
    cudaGetSymbolAddress((void**)&p_w2l,  g_w2l);

    // 1) pooling (count-sort) + weight prep
    k_zero_cnt<<<8, 256>>>();
    k_prep_w<<<256, 256>>>(mW1, mW2, Wq, Wk, Wv, bq, bk, bv);
    k_count<<<SS*NN/256, 256>>>(pid);
    k_scan<<<1, 256>>>();
    k_scatter<<<SS*NN/256, 256>>>(pid);
    k_patchsum<<<SS*KK, 256>>>(H);

    // 2) patch transformer
    k_ln<<<SS*KK, 256>>>(p_x, ln1g, ln1b, p_y);
    dim3 gqkv(QKVW/64, (SS*KK)/64);            // (12, 32)
    k_gemm64<<<gqkv, 256>>>(p_y, p_wqkv, p_bqkv, p_qkv, SS*KK, QKVW, DD, 6, nullptr);
    k_kvsum<<<SS*NHH, 256>>>();
    k_attn<<<SS*KK, 256>>>();
    dim3 g64(DD/64, (SS*KK)/64);               // (4, 32)
    k_gemm64<<<g64, 256>>>(p_attn, Wo, bo, p_x2, SS*KK, DD, DD, 4, p_x);
    k_ln<<<SS*KK, 256>>>(p_x2, ln2g, ln2b, p_y);
    dim3 gf1(FF/64, (SS*KK)/64);               // (16, 32)
    k_gemm64<<<gf1, 256>>>(p_y, fW1, fb1, p_h, SS*KK, FF, DD, 5, nullptr);
    k_gemm64<<<g64, 256>>>(p_h, fW2, fb2, psu, SS*KK, DD, FF, 4, p_x2);

    // 3) node MLP via tensor cores (mma.sync bf16x3)
    k_gemm64<<<g64, 256>>>(psu, mW1 + DD*DD, mb1, p_p2, SS*KK, DD, DD, 0, nullptr);
    dim3 gb(DD/128, (SS*NN)/128);              // (2, 1024)
    k_mma<<<gb, 256>>>(H,     p_w1h, p_w1l, p_hid, 1, p_p2, pid, nullptr, nullptr);
    k_mma<<<gb, 256>>>(p_hid, p_w2h, p_w2l, out,   2, nullptr, nullptr, mb2, H);
}

// round 6
// speedup vs baseline: 1.8647x; 1.0174x over previous
#include <cuda_runtime.h>
#include <cuda_bf16.h>
#include <math.h>
#include <stdint.h>

// Problem constants
#define SS  4
#define NN  32768
#define DD  256
#define KK  512
#define NHH 4
#define HDD 64
#define FF  1024
#define QKVW 768

// ---------------- scratch (device globals; no runtime allocation) ----------------
__device__ float g_x   [SS*KK*DD];
__device__ int   g_cnt [SS*KK];
__device__ int   g_off [SS*KK];
__device__ int   g_cur [SS*KK];
__device__ int   g_nlist[SS*NN];
__device__ float g_y   [SS*KK*DD];
__device__ float g_qkv [SS*KK*QKVW];
__device__ float g_kv  [SS*NHH*HDD*HDD];
__device__ float g_ksum[SS*NHH*HDD];
__device__ float g_attn[SS*KK*DD];
__device__ float g_x2  [SS*KK*DD];
__device__ float g_h   [SS*KK*FF];
__device__ float g_p2  [SS*KK*DD];
__device__ float g_hid [SS*NN*DD];          // node MLP hidden (fp32)
__device__ float g_bqkv[QKVW];

// bf16 hi/lo split weights, all [n][k] layout
__device__ __nv_bfloat16 g_wqkvh[QKVW*DD], g_wqkvl[QKVW*DD];
__device__ __nv_bfloat16 g_woh [DD*DD],   g_wol [DD*DD];
__device__ __nv_bfloat16 g_f1h [FF*DD],   g_f1l [FF*DD];
__device__ __nv_bfloat16 g_f2h [DD*FF],   g_f2l [DD*FF];
__device__ __nv_bfloat16 g_p2h [DD*DD],   g_p2l [DD*DD];   // mW1[256:512]
__device__ __nv_bfloat16 g_w1h [DD*DD],   g_w1l [DD*DD];   // mW1[0:256]
__device__ __nv_bfloat16 g_w2h [DD*DD],   g_w2l [DD*DD];   // mW2

// ---------------- small device helpers ----------------
__device__ __forceinline__ float geluf(float x) {
    return 0.5f * x * (1.0f + erff(x * 0.70710678118654752440f));
}
__device__ __forceinline__ float phif(float x) {   // elu(x)+1
    return x > 0.0f ? x + 1.0f : expf(x);
}
__device__ __forceinline__ uint32_t pack_bf2(float a, float b) {
    __nv_bfloat162 t = __floats2bfloat162_rn(a, b);
    return *(uint32_t*)&t;
}
__device__ __forceinline__ float bflo(uint32_t p) {
    __nv_bfloat162 b = *(__nv_bfloat162*)&p; return __bfloat162float(b.x);
}
__device__ __forceinline__ float bfhi(uint32_t p) {
    __nv_bfloat162 b = *(__nv_bfloat162*)&p; return __bfloat162float(b.y);
}
__device__ __forceinline__ uint32_t smem_u32(const void* p) {
    uint32_t a;
    asm("{ .reg .u64 t; cvta.to.shared.u64 t, %1; cvt.u32.u64 %0, t; }" : "=r"(a) : "l"(p));
    return a;
}
#define LDSM_X4(r0, r1, r2, r3, addr) \
    asm volatile("ldmatrix.sync.aligned.m8n8.x4.shared.b16 {%0,%1,%2,%3}, [%4];" \
                 : "=r"(r0), "=r"(r1), "=r"(r2), "=r"(r3) : "r"(addr))
#define MMA_BF16(d, a, b) \
    asm volatile("mma.sync.aligned.m16n8k16.row.col.f32.bf16.bf16.f32 " \
                 "{%0,%1,%2,%3},{%4,%5,%6,%7},{%8,%9},{%0,%1,%2,%3};" \
                 : "+f"((d)[0]), "+f"((d)[1]), "+f"((d)[2]), "+f"((d)[3]) \
                 : "r"((a)[0]), "r"((a)[1]), "r"((a)[2]), "r"((a)[3]), \
                   "r"((b)[0]), "r"((b)[1]))

// ---------------- pooling (count-sort, no fp32 atomics) ----------------
__global__ void k_zero_cnt() {
    int i = blockIdx.x * blockDim.x + threadIdx.x;
    if (i < SS*KK) g_cnt[i] = 0;
}

__global__ void k_count(const int* __restrict__ pid) {
    int b = blockIdx.x * blockDim.x + threadIdx.x;
    int s = b >> 15;
    atomicAdd(&g_cnt[s*KK + pid[b]], 1);
}

__global__ void k_scan() {
    __shared__ int part[256];
    int t = threadIdx.x;
    int base = t * 8;
    int loc[8];
    int sum = 0;
    #pragma unroll
    for (int i = 0; i < 8; i++) { loc[i] = sum; sum += g_cnt[base + i]; }
    part[t] = sum;
    __syncthreads();
    #pragma unroll
    for (int off = 1; off < 256; off <<= 1) {
        int v = (t >= off) ? part[t - off] : 0;
        __syncthreads();
        part[t] += v;
        __syncthreads();
    }
    int prev = (t > 0) ? part[t - 1] : 0;
    #pragma unroll
    for (int i = 0; i < 8; i++) {
        g_off[base + i] = prev + loc[i];
        g_cur[base + i] = prev + loc[i];
    }
}

__global__ void k_scatter(const int* __restrict__ pid) {
    int b = blockIdx.x * blockDim.x + threadIdx.x;
    int s = b >> 15;
    int pos = atomicAdd(&g_cur[s*KK + pid[b]], 1);
    g_nlist[pos] = b;
}

__global__ __launch_bounds__(256) void k_patchsum(const float* __restrict__ H) {
    int r = blockIdx.x;
    int d = threadIdx.x;
    int cnt = g_cnt[r];
    int off = g_off[r];
    float a0 = 0.f, a1 = 0.f, a2 = 0.f, a3 = 0.f;
    int i = 0;
    for (; i + 4 <= cnt; i += 4) {
        int n0 = g_nlist[off+i],   n1 = g_nlist[off+i+1];
        int n2 = g_nlist[off+i+2], n3 = g_nlist[off+i+3];
        a0 += __ldg(&H[(size_t)n0*DD + d]);
        a1 += __ldg(&H[(size_t)n1*DD + d]);
        a2 += __ldg(&H[(size_t)n2*DD + d]);
        a3 += __ldg(&H[(size_t)n3*DD + d]);
    }
    for (; i < cnt; i++) a0 += __ldg(&H[(size_t)g_nlist[off+i]*DD + d]);
    float sum = (a0 + a1) + (a2 + a3);
    float inv = (cnt > 0) ? (1.0f / (float)cnt) : 0.0f;
    g_x[(size_t)r*DD + d] = sum * inv;
}

// ---------------- weight prep: split everything to bf16 hi/lo, [n][k] ----------------
// grid rows (blockIdx.x):
//   [0,768)      qkv   (Wq|Wk|Wv), K=256; also bias concat
//   [768,1024)   Wo,  K=256
//   [1024,2048)  fW1, K=256
//   [2048,2304)  fW2, K=1024
//   [2304,2560)  mW1b (rows 256:512), K=256
//   [2560,2816)  mW1a (rows 0:256),  K=256
//   [2816,3072)  mW2, K=256
__global__ void k_prep_w(const float* __restrict__ Wq, const float* __restrict__ Wk,
                         const float* __restrict__ Wv, const float* __restrict__ bq,
                         const float* __restrict__ bk, const float* __restrict__ bv,
                         const float* __restrict__ Wo, const float* __restrict__ fW1,
                         const float* __restrict__ fW2, const float* __restrict__ mW1,
                         const float* __restrict__ mW2) {
    int r = blockIdx.x, t = threadIdx.x;
    if (r < 768) {
        int n = r;
        float v = (n < 256) ? Wq[t*DD + n] : (n < 512) ? Wk[t*DD + (n-256)] : Wv[t*DD + (n-512)];
        __nv_bfloat16 h = __float2bfloat16(v);
        g_wqkvh[n*DD + t] = h;
        g_wqkvl[n*DD + t] = __float2bfloat16(v - __bfloat162float(h));
        if (t == 0) g_bqkv[n] = (n < 256) ? bq[n] : (n < 512) ? bk[n-256] : bv[n-512];
    } else if (r < 1024) {
        int n = r - 768;
        float v = Wo[t*DD + n];
        __nv_bfloat16 h = __float2bfloat16(v);
        g_woh[n*DD + t] = h;
        g_wol[n*DD + t] = __float2bfloat16(v - __bfloat162float(h));
    } else if (r < 2048) {
        int n = r - 1024;
        float v = fW1[t*FF + n];
        __nv_bfloat16 h = __float2bfloat16(v);
        g_f1h[n*DD + t] = h;
        g_f1l[n*DD + t] = __float2bfloat16(v - __bfloat162float(h));
    } else if (r < 2304) {
        int n = r - 2048;
        #pragma unroll
        for (int kk = 0; kk < 4; kk++) {
            int k = t + kk*256;
            float v = fW2[k*DD + n];
            __nv_bfloat16 h = __float2bfloat16(v);
            g_f2h[n*FF + k] = h;
            g_f2l[n*FF + k] = __float2bfloat16(v - __bfloat162float(h));
        }
    } else if (r < 2560) {
        int n = r - 2304;
        float v = mW1[(256 + t)*DD + n];
        __nv_bfloat16 h = __float2bfloat16(v);
        g_p2h[n*DD + t] = h;
        g_p2l[n*DD + t] = __float2bfloat16(v - __bfloat162float(h));
    } else if (r < 2816) {
        int n = r - 2560;
        float v = mW1[t*DD + n];
        __nv_bfloat16 h = __float2bfloat16(v);
        g_w1h[n*DD + t] = h;
        g_w1l[n*DD + t] = __float2bfloat16(v - __bfloat162float(h));
    } else {
        int n = r - 2816;
        float v = mW2[t*DD + n];
        __nv_bfloat16 h = __float2bfloat16(v);
        g_w2h[n*DD + t] = h;
        g_w2l[n*DD + t] = __float2bfloat16(v - __bfloat162float(h));
    }
}

// ---------------- layer norm ----------------
__global__ void k_ln(const float* __restrict__ in, const float* __restrict__ gw,
                     const float* __restrict__ bw, float* __restrict__ out) {
    int r = blockIdx.x, d = threadIdx.x;
    float v = in[(size_t)r*DD + d];
    __shared__ float s1[8], s2[8];
    __shared__ float smu, sri;
    float a = v, b = v * v;
    #pragma unroll
    for (int o = 16; o > 0; o >>= 1) {
        a += __shfl_down_sync(0xffffffffu, a, o);
        b += __shfl_down_sync(0xffffffffu, b, o);
    }
    if ((d & 31) == 0) { s1[d >> 5] = a; s2[d >> 5] = b; }
    __syncthreads();
    if (d == 0) {
        float sa = 0.f, sb = 0.f;
        #pragma unroll
        for (int i = 0; i < 8; i++) { sa += s1[i]; sb += s2[i]; }
        float m   = sa * (1.0f / DD);
        float var = sb * (1.0f / DD) - m * m;
        smu = m; sri = rsqrtf(var + 1e-5f);
    }
    __syncthreads();
    out[(size_t)r*DD + d] = (v - smu) * sri * gw[d] + bw[d];
}

__global__ __launch_bounds__(256) void k_kvsum() {
    int b = blockIdx.x;
    int s = b >> 2, h = b & 3;
    int t = threadIdx.x, tx = t & 15, ty = t >> 4;
    __shared__ float ks[8][64], vs[8][64];
    float acc[4][4] = {};
    float ksl = 0.0f;
    const float* kp = g_qkv + (size_t)s*KK*QKVW + 256 + h*HDD;
    const float* vp = g_qkv + (size_t)s*KK*QKVW + 512 + h*HDD;

    for (int k0 = 0; k0 < KK; k0 += 8) {
        #pragma unroll
        for (int u = 0; u < 2; u++) {
            int idx = t + u*256; int i = idx >> 6, d = idx & 63;
            ks[i][d] = kp[(size_t)(k0 + i)*QKVW + d];
            vs[i][d] = vp[(size_t)(k0 + i)*QKVW + d];
        }
        __syncthreads();
        if (t < 64) {
            #pragma unroll
            for (int i = 0; i < 8; i++) ksl += ks[i][t];
        }
        #pragma unroll
        for (int i = 0; i < 8; i++) {
            float kd[4], ve[4];
            #pragma unroll
            for (int j = 0; j < 4; j++) { kd[j] = ks[i][ty*4+j]; ve[j] = vs[i][tx*4+j]; }
            #pragma unroll
            for (int a = 0; a < 4; a++)
                #pragma unroll
                for (int c = 0; c < 4; c++)
                    acc[a][c] += kd[a] * ve[c];
        }
        __syncthreads();
    }
    if (t < 64) g_ksum[(size_t)b*64 + t] = ksl;
    #pragma unroll
    for (int a = 0; a < 4; a++)
        #pragma unroll
        for (int c = 0; c < 4; c++)
            g_kv[((size_t)b*64 + ty*4 + a)*64 + tx*4 + c] = acc[a][c];
}

__global__ void k_attn() {
    int r = blockIdx.x;
    int s = r / KK;
    int t = threadIdx.x;
    __shared__ float qs[256];
    qs[t] = g_qkv[(size_t)r*QKVW + t];
    __syncthreads();
    int h = t >> 6, e = t & 63;
    const float* kvp = g_kv   + (size_t)(s*NHH + h)*HDD*HDD;
    const float* ksp = g_ksum + (size_t)(s*NHH + h)*HDD;
    float num = 0.f, den = 0.f;
    #pragma unroll 8
    for (int d = 0; d < 64; d++) {
        float q = qs[h*64 + d];
        num += q * kvp[d*64 + e];
        den += q * ksp[d];
    }
    g_attn[(size_t)r*DD + t] = num / (den + 1e-6f);
}

// ---- Generic tensor-core GEMM (mma.sync bf16x3): C = epi(A[M,Kd] @ Bt^T) ----
// A fp32 row-major [M][Kd]; Bt bf16 hi/lo [Ncols][Kd]; C fp32 [M][Cld].
// Tile: CTA 128x128, warp 32x64, K-chunk 32.
// modes: 0: C=acc+bias
//        1: C=gelu(acc + p2[(s*KK+pid[m])*256 + col])     (node GEMM1)
//        2: C=acc+bias+res (res stride = Cld)
//        5: C=gelu(acc+bias)
//        6: qkv: col<256 phi, col<512 phi*mask, else *mask (bias added first)
__global__ __launch_bounds__(256, 2) void k_mma(
    const float* __restrict__ A,
    const __nv_bfloat16* __restrict__ Bh,
    const __nv_bfloat16* __restrict__ Bl,
    float* __restrict__ C, int Kd, int Cld, int mode,
    const float* __restrict__ p2, const int* __restrict__ pid,
    const float* __restrict__ bias, const float* __restrict__ res)
{
    __shared__ __nv_bfloat16 Ash[128][40];
    __shared__ __nv_bfloat16 Asl[128][40];
    __shared__ __nv_bfloat16 Bsh[128][40];
    __shared__ __nv_bfloat16 Bsl[128][40];

    const int t = threadIdx.x, lane = t & 31, wid = t >> 5;
    const int n0 = blockIdx.x * 128, m0 = blockIdx.y * 128;
    const int wm = (wid & 3) * 32;
    const int wn = (wid >> 2) * 64;

    const uint32_t sAh = smem_u32(Ash), sAl = smem_u32(Asl);
    const uint32_t sBh = smem_u32(Bsh), sBl = smem_u32(Bsl);

    const int a_m = wm + (lane & 15);
    const int a_k = (lane >> 4) << 3;
    const int b_n = wn + ((lane >> 4) << 3) + (lane & 7);
    const int b_k = ((lane >> 3) & 1) << 3;

    float acc[2][8][4] = {};
    const int nchunks = Kd >> 5;

    for (int c = 0; c < nchunks; c++) {
        const int k0 = c * 32;
        #pragma unroll
        for (int i = 0; i < 4; i++) {
            int lin = t + 256 * i;
            int row = lin >> 3, q = lin & 7;
            float4 f = *(const float4*)(A + (size_t)(m0 + row)*Kd + k0 + q*4);
            uint32_t h01 = pack_bf2(f.x, f.y);
            uint32_t h23 = pack_bf2(f.z, f.w);
            uint32_t l01 = pack_bf2(f.x - bflo(h01), f.y - bfhi(h01));
            uint32_t l23 = pack_bf2(f.z - bflo(h23), f.w - bfhi(h23));
            *(uint2*)&Ash[row][q*4] = make_uint2(h01, h23);
            *(uint2*)&Asl[row][q*4] = make_uint2(l01, l23);
        }
        #pragma unroll
        for (int i = 0; i < 2; i++) {
            int lin = t + 256 * i;
            int row = lin >> 2, q = lin & 3;
            *(uint4*)&Bsh[row][q*8] = *(const uint4*)(Bh + (size_t)(n0 + row)*Kd + k0 + q*8);
            *(uint4*)&Bsl[row][q*8] = *(const uint4*)(Bl + (size_t)(n0 + row)*Kd + k0 + q*8);
        }
        __syncthreads();

        #pragma unroll
        for (int kk = 0; kk < 2; kk++) {
            uint32_t ah[2][4], al[2][4];
            #pragma unroll
            for (int mt = 0; mt < 2; mt++) {
                uint32_t offA = (uint32_t)((a_m + mt*16) * 40 + kk*16 + a_k) * 2;
                LDSM_X4(ah[mt][0], ah[mt][1], ah[mt][2], ah[mt][3], sAh + offA);
                LDSM_X4(al[mt][0], al[mt][1], al[mt][2], al[mt][3], sAl + offA);
            }
            #pragma unroll
            for (int g = 0; g < 4; g++) {
                uint32_t offB = (uint32_t)((b_n + g*16) * 40 + kk*16 + b_k) * 2;
                uint32_t bh[2][2], bl[2][2];
                LDSM_X4(bh[0][0], bh[0][1], bh[1][0], bh[1][1], sBh + offB);
                LDSM_X4(bl[0][0], bl[0][1], bl[1][0], bl[1][1], sBl + offB);
                #pragma unroll
                for (int mt = 0; mt < 2; mt++) {
                    #pragma unroll
                    for (int j = 0; j < 2; j++) {
                        float* d = acc[mt][g*2 + j];
                        MMA_BF16(d, ah[mt], bh[j]);
                        MMA_BF16(d, ah[mt], bl[j]);
                        MMA_BF16(d, al[mt], bh[j]);
                    }
                }
            }
        }
        __syncthreads();
    }

    const int lr = lane >> 2;
    const int lc = (lane & 3) * 2;
    #pragma unroll
    for (int mt = 0; mt < 2; mt++) {
        int mrow0 = m0 + wm + mt*16 + lr;
        int mrow1 = mrow0 + 8;
        if (mode == 1) {
            int s = mrow0 >> 15;
            const float* p2r0 = p2 + ((size_t)(s*KK + pid[mrow0]))*DD;
            const float* p2r1 = p2 + ((size_t)(s*KK + pid[mrow1]))*DD;
            #pragma unroll
            for (int nt = 0; nt < 8; nt++) {
                int col = n0 + wn + nt*8 + lc;
                float2 o0, o1;
                o0.x = geluf(acc[mt][nt][0] + p2r0[col]);
                o0.y = geluf(acc[mt][nt][1] + p2r0[col+1]);
                o1.x = geluf(acc[mt][nt][2] + p2r1[col]);
                o1.y = geluf(acc[mt][nt][3] + p2r1[col+1]);
                *(float2*)(C + (size_t)mrow0*Cld + col) = o0;
                *(float2*)(C + (size_t)mrow1*Cld + col) = o1;
            }
        } else if (mode == 2) {
            #pragma unroll
            for (int nt = 0; nt < 8; nt++) {
                int col = n0 + wn + nt*8 + lc;
                float2 bv = *(const float2*)(bias + col);
                float2 r0 = *(const float2*)(res + (size_t)mrow0*Cld + col);
                float2 r1 = *(const float2*)(res + (size_t)mrow1*Cld + col);
                float2 o0, o1;
                o0.x = acc[mt][nt][0] + bv.x + r0.x;
                o0.y = acc[mt][nt][1] + bv.y + r0.y;
                o1.x = acc[mt][nt][2] + bv.x + r1.x;
                o1.y = acc[mt][nt][3] + bv.y + r1.y;
                *(float2*)(C + (size_t)mrow0*Cld + col) = o0;
                *(float2*)(C + (size_t)mrow1*Cld + col) = o1;
            }
        } else if (mode == 5) {
            #pragma unroll
            for (int nt = 0; nt < 8; nt++) {
                int col = n0 + wn + nt*8 + lc;
                float2 bv = *(const float2*)(bias + col);
                float2 o0, o1;
                o0.x = geluf(acc[mt][nt][0] + bv.x);
                o0.y = geluf(acc[mt][nt][1] + bv.y);
                o1.x = geluf(acc[mt][nt][2] + bv.x);
                o1.y = geluf(acc[mt][nt][3] + bv.y);
                *(float2*)(C + (size_t)mrow0*Cld + col) = o0;
                *(float2*)(C + (size_t)mrow1*Cld + col) = o1;
            }
        } else if (mode == 6) {
            float mk0 = (g_cnt[mrow0] > 0) ? 1.0f : 0.0f;
            float mk1 = (g_cnt[mrow1] > 0) ? 1.0f : 0.0f;
            #pragma unroll
            for (int nt = 0; nt < 8; nt++) {
                int col = n0 + wn + nt*8 + lc;
                float2 bv = *(const float2*)(bias + col);
                float v00 = acc[mt][nt][0] + bv.x, v01 = acc[mt][nt][1] + bv.y;
                float v10 = acc[mt][nt][2] + bv.x, v11 = acc[mt][nt][3] + bv.y;
                float2 o0, o1;
                if (col < 256) {
                    o0.x = phif(v00); o0.y = phif(v01);
                    o1.x = phif(v10); o1.y = phif(v11);
                } else if (col < 512) {
                    o0.x = phif(v00) * mk0; o0.y = phif(v01) * mk0;
                    o1.x = phif(v10) * mk1; o1.y = phif(v11) * mk1;
                } else {
                    o0.x = v00 * mk0; o0.y = v01 * mk0;
                    o1.x = v10 * mk1; o1.y = v11 * mk1;
                }
                *(float2*)(C + (size_t)mrow0*Cld + col) = o0;
                *(float2*)(C + (size_t)mrow1*Cld + col) = o1;
            }
        } else { // mode 0
            #pragma unroll
            for (int nt = 0; nt < 8; nt++) {
                int col = n0 + wn + nt*8 + lc;
                float2 bv = *(const float2*)(bias + col);
                float2 o0, o1;
                o0.x = acc[mt][nt][0] + bv.x;
                o0.y = acc[mt][nt][1] + bv.y;
                o1.x = acc[mt][nt][2] + bv.x;
                o1.y = acc[mt][nt][3] + bv.y;
                *(float2*)(C + (size_t)mrow0*Cld + col) = o0;
                *(float2*)(C + (size_t)mrow1*Cld + col) = o1;
            }
        }
    }
}

// ---------------- launch ----------------
extern "C" void kernel_launch(void* const* d_in, const int* in_sizes, int n_in,
                              void* d_out, int out_size) {
    (void)in_sizes; (void)n_in; (void)out_size;
    const float* H    = (const float*)d_in[0];
    const int*   pid  = (const int*)  d_in[1];
    const float* ln1g = (const float*)d_in[2];
    const float* ln1b = (const float*)d_in[3];
    const float* Wq   = (const float*)d_in[4];
    const float* bq   = (const float*)d_in[5];
    const float* Wk   = (const float*)d_in[6];
    const float* bk   = (const float*)d_in[7];
    const float* Wv   = (const float*)d_in[8];
    const float* bv   = (const float*)d_in[9];
    const float* Wo   = (const float*)d_in[10];
    const float* bo   = (const float*)d_in[11];
    const float* ln2g = (const float*)d_in[12];
    const float* ln2b = (const float*)d_in[13];
    const float* fW1  = (const float*)d_in[14];
    const float* fb1  = (const float*)d_in[15];
    const float* fW2  = (const float*)d_in[16];
    const float* fb2  = (const float*)d_in[17];
    const float* mW1  = (const float*)d_in[18];
    const float* mb1  = (const float*)d_in[19];
    const float* mW2  = (const float*)d_in[20];
    const float* mb2  = (const float*)d_in[21];

    float* out = (float*)d_out;
    float* psu = out + (size_t)SS*NN*DD;

    float *p_x, *p_y, *p_qkv, *p_attn, *p_x2, *p_h, *p_p2, *p_hid, *p_bqkv;
    __nv_bfloat16 *p_wqkvh, *p_wqkvl, *p_woh, *p_wol, *p_f1h, *p_f1l, *p_f2h, *p_f2l;
    __nv_bfloat16 *p_p2h, *p_p2l, *p_w1h, *p_w1l, *p_w2h, *p_w2l;
    cudaGetSymbolAddress((void**)&p_x,     g_x);
    cudaGetSymbolAddress((void**)&p_y,     g_y);
    cudaGetSymbolAddress((void**)&p_qkv,   g_qkv);
    cudaGetSymbolAddress((void**)&p_attn,  g_attn);
    cudaGetSymbolAddress((void**)&p_x2,    g_x2);
    cudaGetSymbolAddress((void**)&p_h,     g_h);
    cudaGetSymbolAddress((void**)&p_p2,    g_p2);
    cudaGetSymbolAddress((void**)&p_hid,   g_hid);
    cudaGetSymbolAddress((void**)&p_bqkv,  g_bqkv);
    cudaGetSymbolAddress((void**)&p_wqkvh, g_wqkvh);
    cudaGetSymbolAddress((void**)&p_wqkvl, g_wqkvl);
    cudaGetSymbolAddress((void**)&p_woh,   g_woh);
    cudaGetSymbolAddress((void**)&p_wol,   g_wol);
    cudaGetSymbolAddress((void**)&p_f1h,   g_f1h);
    cudaGetSymbolAddress((void**)&p_f1l,   g_f1l);
    cudaGetSymbolAddress((void**)&p_f2h,   g_f2h);
    cudaGetSymbolAddress((void**)&p_f2l,   g_f2l);
    cudaGetSymbolAddress((void**)&p_p2h,   g_p2h);
    cudaGetSymbolAddress((void**)&p_p2l,   g_p2l);
    cudaGetSymbolAddress((void**)&p_w1h,   g_w1h);
    cudaGetSymbolAddress((void**)&p_w1l,   g_w1l);
    cudaGetSymbolAddress((void**)&p_w2h,   g_w2h);
    cudaGetSymbolAddress((void**)&p_w2l,   g_w2l);

    // 1) pooling (count-sort) + weight prep
    k_zero_cnt<<<8, 256>>>();
    k_prep_w<<<3072, 256>>>(Wq, Wk, Wv, bq, bk, bv, Wo, fW1, fW2, mW1, mW2);
    k_count<<<SS*NN/256, 256>>>(pid);
    k_scan<<<1, 256>>>();
    k_scatter<<<SS*NN/256, 256>>>(pid);
    k_patchsum<<<SS*KK, 256>>>(H);

    // 2) patch transformer (all GEMMs on tensor cores)
    k_ln<<<SS*KK, 256>>>(p_x, ln1g, ln1b, p_y);
    k_mma<<<dim3(QKVW/128, (SS*KK)/128), 256>>>(p_y, p_wqkvh, p_wqkvl, p_qkv,
                                                DD, QKVW, 6, nullptr, nullptr, p_bqkv, nullptr);
    k_kvsum<<<SS*NHH, 256>>>();
    k_attn<<<SS*KK, 256>>>();
    k_mma<<<dim3(DD/128, (SS*KK)/128), 256>>>(p_attn, p_woh, p_wol, p_x2,
                                              DD, DD, 2, nullptr, nullptr, bo, p_x);
    k_ln<<<SS*KK, 256>>>(p_x2, ln2g, ln2b, p_y);
    k_mma<<<dim3(FF/128, (SS*KK)/128), 256>>>(p_y, p_f1h, p_f1l, p_h,
                                              DD, FF, 5, nullptr, nullptr, fb1, nullptr);
    k_mma<<<dim3(DD/128, (SS*KK)/128), 256>>>(p_h, p_f2h, p_f2l, psu,
                                              FF, DD, 2, nullptr, nullptr, fb2, p_x2);

    // 3) node MLP via tensor cores
    k_mma<<<dim3(DD/128, (SS*KK)/128), 256>>>(psu, p_p2h, p_p2l, p_p2,
                                              DD, DD, 0, nullptr, nullptr, mb1, nullptr);
    dim3 gb(DD/128, (SS*NN)/128);
    k_mma<<<gb, 256>>>(H,     p_w1h, p_w1l, p_hid, DD, DD, 1, p_p2, pid, nullptr, nullptr);
    k_mma<<<gb, 256>>>(p_hid, p_w2h, p_w2l, out,   DD, DD, 2, nullptr, nullptr, mb2, H);
}